// round 16
// baseline (speedup 1.0000x reference)
#include <cuda_runtime.h>

// Round 16: exactly R15 (two segments per block, joint reduce) with ONE change:
// default (write-back) stores instead of __stcs streaming stores. out is
// rewritten every graph replay; keeping its lines L2-resident lets dirty lines
// be overwritten in place instead of streaming 64MB to DRAM each replay.

#define T 128
#define NW (T / 32)

__device__ __forceinline__ float sum_exp_range(const float* __restrict__ logits,
                                               int start, int end, int tid) {
    int astart = (start + 3) & ~3; if (astart > end) astart = end;
    int aend   = end & ~3;         if (aend < astart) aend = astart;

    const float4* __restrict__ logits4 = (const float4*)logits;
    const int STEP = T * 4;

    float s = 0.0f;
    for (int i = start + tid; i < astart; i += T)
        s += __expf(__ldg(&logits[i]));

    int i = astart + tid * 4;
    for (; i + 3 * STEP < aend; i += 4 * STEP) {
        float4 v0 = __ldg(&logits4[(i           ) >> 2]);
        float4 v1 = __ldg(&logits4[(i +     STEP) >> 2]);
        float4 v2 = __ldg(&logits4[(i + 2 * STEP) >> 2]);
        float4 v3 = __ldg(&logits4[(i + 3 * STEP) >> 2]);
        s += __expf(v0.x) + __expf(v0.y) + __expf(v0.z) + __expf(v0.w);
        s += __expf(v1.x) + __expf(v1.y) + __expf(v1.z) + __expf(v1.w);
        s += __expf(v2.x) + __expf(v2.y) + __expf(v2.z) + __expf(v2.w);
        s += __expf(v3.x) + __expf(v3.y) + __expf(v3.z) + __expf(v3.w);
    }
    for (; i < aend; i += STEP) {
        float4 v = __ldg(&logits4[i >> 2]);
        s += __expf(v.x) + __expf(v.y) + __expf(v.z) + __expf(v.w);
    }
    for (int j = aend + tid; j < end; j += T)
        s += __expf(__ldg(&logits[j]));
    return s;
}

__device__ __forceinline__ void write_range(const float* __restrict__ logits,
                                            float* __restrict__ out,
                                            int start, int end, int tid, float lse) {
    int astart = (start + 3) & ~3; if (astart > end) astart = end;
    int aend   = end & ~3;         if (aend < astart) aend = astart;

    const float4* __restrict__ logits4 = (const float4*)logits;
    float4*       __restrict__ out4    = (float4*)out;
    const int STEP = T * 4;

    for (int j = start + tid; j < astart; j += T)
        out[j] = __ldg(&logits[j]) - lse;

    int i = astart + tid * 4;
    for (; i + 3 * STEP < aend; i += 4 * STEP) {
        float4 v0 = __ldg(&logits4[(i           ) >> 2]);
        float4 v1 = __ldg(&logits4[(i +     STEP) >> 2]);
        float4 v2 = __ldg(&logits4[(i + 2 * STEP) >> 2]);
        float4 v3 = __ldg(&logits4[(i + 3 * STEP) >> 2]);
        float4 r0, r1, r2, r3;
        r0.x = v0.x - lse; r0.y = v0.y - lse; r0.z = v0.z - lse; r0.w = v0.w - lse;
        r1.x = v1.x - lse; r1.y = v1.y - lse; r1.z = v1.z - lse; r1.w = v1.w - lse;
        r2.x = v2.x - lse; r2.y = v2.y - lse; r2.z = v2.z - lse; r2.w = v2.w - lse;
        r3.x = v3.x - lse; r3.y = v3.y - lse; r3.z = v3.z - lse; r3.w = v3.w - lse;
        out4[(i           ) >> 2] = r0;
        out4[(i +     STEP) >> 2] = r1;
        out4[(i + 2 * STEP) >> 2] = r2;
        out4[(i + 3 * STEP) >> 2] = r3;
    }
    for (; i < aend; i += STEP) {
        float4 v = __ldg(&logits4[i >> 2]);
        float4 r;
        r.x = v.x - lse; r.y = v.y - lse; r.z = v.z - lse; r.w = v.w - lse;
        out4[i >> 2] = r;
    }
    for (int j = aend + tid; j < end; j += T)
        out[j] = __ldg(&logits[j]) - lse;
}

__global__ void __launch_bounds__(T)
jagged_log_softmax_kernel(const float* __restrict__ logits,
                          const int* __restrict__ prefix_sum,
                          float* __restrict__ out,
                          int nseg) {
    __shared__ float sm[2][NW];
    __shared__ float s_lse[2];

    const int tid  = threadIdx.x;
    const int lane = tid & 31;
    const int warp = tid >> 5;

    const int segA = blockIdx.x;
    const int segB = blockIdx.x + gridDim.x;

    const int startA = (segA == 0) ? 0 : __ldg(&prefix_sum[segA - 1]);
    const int endA   = __ldg(&prefix_sum[segA]);
    const bool hasB  = (segB < nseg);
    const int startB = hasB ? __ldg(&prefix_sum[segB - 1]) : 0;
    const int endB   = hasB ? __ldg(&prefix_sum[segB]) : 0;

    const bool doA = (startA < endA);
    const bool doB = hasB && (startB < endB);

    // ---- pass 1 for both segments ----
    float sa = doA ? sum_exp_range(logits, startA, endA, tid) : 0.0f;
    float sb = doB ? sum_exp_range(logits, startB, endB, tid) : 0.0f;

    // ---- joint block reduce ----
    #pragma unroll
    for (int o = 16; o > 0; o >>= 1) {
        sa += __shfl_xor_sync(0xFFFFFFFFu, sa, o);
        sb += __shfl_xor_sync(0xFFFFFFFFu, sb, o);
    }
    if (lane == 0) { sm[0][warp] = sa; sm[1][warp] = sb; }
    __syncthreads();
    if (warp == 0) {
        float v = (lane < NW) ? sm[0][lane] : 0.0f;
        #pragma unroll
        for (int o = NW / 2; o > 0; o >>= 1)
            v += __shfl_xor_sync(0xFFFFFFFFu, v, o);
        if (lane == 0) s_lse[0] = __logf(v);
    } else if (warp == 1) {
        float v = (lane < NW) ? sm[1][lane] : 0.0f;
        #pragma unroll
        for (int o = NW / 2; o > 0; o >>= 1)
            v += __shfl_xor_sync(0xFFFFFFFFu, v, o);
        if (lane == 0) s_lse[1] = __logf(v);
    }
    __syncthreads();

    // ---- pass 2 for both segments ----
    if (doA) write_range(logits, out, startA, endA, tid, s_lse[0]);
    if (doB) write_range(logits, out, startB, endB, tid, s_lse[1]);
}

extern "C" void kernel_launch(void* const* d_in, const int* in_sizes, int n_in,
                              void* d_out, int out_size) {
    const float* logits     = (const float*)d_in[0];
    const int*   prefix_sum = (const int*)d_in[1];
    float*       out        = (float*)d_out;

    const int num_segs = in_sizes[1];
    const int grid     = (num_segs + 1) / 2;
    jagged_log_softmax_kernel<<<grid, T>>>(logits, prefix_sum, out, num_segs);
}

// round 17
// speedup vs baseline: 1.0136x; 1.0136x over previous
#include <cuda_runtime.h>

// Round 17: R15 extended to FOUR segments per block (A..D = bid + k*grid).
// One joint block reduce for all four sums; pass1 x4 back-to-back (long load
// burst), pass2 x4. __stcs streaming stores (R16 proved write-back worse).

#define T 128
#define NW (T / 32)

__device__ __forceinline__ float sum_exp_range(const float* __restrict__ logits,
                                               int start, int end, int tid) {
    int astart = (start + 3) & ~3; if (astart > end) astart = end;
    int aend   = end & ~3;         if (aend < astart) aend = astart;

    const float4* __restrict__ logits4 = (const float4*)logits;
    const int STEP = T * 4;

    float s = 0.0f;
    for (int i = start + tid; i < astart; i += T)
        s += __expf(__ldg(&logits[i]));

    int i = astart + tid * 4;
    for (; i + 3 * STEP < aend; i += 4 * STEP) {
        float4 v0 = __ldg(&logits4[(i           ) >> 2]);
        float4 v1 = __ldg(&logits4[(i +     STEP) >> 2]);
        float4 v2 = __ldg(&logits4[(i + 2 * STEP) >> 2]);
        float4 v3 = __ldg(&logits4[(i + 3 * STEP) >> 2]);
        s += __expf(v0.x) + __expf(v0.y) + __expf(v0.z) + __expf(v0.w);
        s += __expf(v1.x) + __expf(v1.y) + __expf(v1.z) + __expf(v1.w);
        s += __expf(v2.x) + __expf(v2.y) + __expf(v2.z) + __expf(v2.w);
        s += __expf(v3.x) + __expf(v3.y) + __expf(v3.z) + __expf(v3.w);
    }
    for (; i < aend; i += STEP) {
        float4 v = __ldg(&logits4[i >> 2]);
        s += __expf(v.x) + __expf(v.y) + __expf(v.z) + __expf(v.w);
    }
    for (int j = aend + tid; j < end; j += T)
        s += __expf(__ldg(&logits[j]));
    return s;
}

__device__ __forceinline__ void write_range(const float* __restrict__ logits,
                                            float* __restrict__ out,
                                            int start, int end, int tid, float lse) {
    int astart = (start + 3) & ~3; if (astart > end) astart = end;
    int aend   = end & ~3;         if (aend < astart) aend = astart;

    const float4* __restrict__ logits4 = (const float4*)logits;
    const int STEP = T * 4;

    for (int j = start + tid; j < astart; j += T)
        __stcs(&out[j], __ldg(&logits[j]) - lse);

    int i = astart + tid * 4;
    for (; i + 3 * STEP < aend; i += 4 * STEP) {
        float4 v0 = __ldg(&logits4[(i           ) >> 2]);
        float4 v1 = __ldg(&logits4[(i +     STEP) >> 2]);
        float4 v2 = __ldg(&logits4[(i + 2 * STEP) >> 2]);
        float4 v3 = __ldg(&logits4[(i + 3 * STEP) >> 2]);
        float4 r0, r1, r2, r3;
        r0.x = v0.x - lse; r0.y = v0.y - lse; r0.z = v0.z - lse; r0.w = v0.w - lse;
        r1.x = v1.x - lse; r1.y = v1.y - lse; r1.z = v1.z - lse; r1.w = v1.w - lse;
        r2.x = v2.x - lse; r2.y = v2.y - lse; r2.z = v2.z - lse; r2.w = v2.w - lse;
        r3.x = v3.x - lse; r3.y = v3.y - lse; r3.z = v3.z - lse; r3.w = v3.w - lse;
        __stcs((float4*)&out[i           ], r0);
        __stcs((float4*)&out[i +     STEP], r1);
        __stcs((float4*)&out[i + 2 * STEP], r2);
        __stcs((float4*)&out[i + 3 * STEP], r3);
    }
    for (; i < aend; i += STEP) {
        float4 v = __ldg(&logits4[i >> 2]);
        float4 r;
        r.x = v.x - lse; r.y = v.y - lse; r.z = v.z - lse; r.w = v.w - lse;
        __stcs((float4*)&out[i], r);
    }
    for (int j = aend + tid; j < end; j += T)
        __stcs(&out[j], __ldg(&logits[j]) - lse);
}

__global__ void __launch_bounds__(T)
jagged_log_softmax_kernel(const float* __restrict__ logits,
                          const int* __restrict__ prefix_sum,
                          float* __restrict__ out,
                          int nseg) {
    __shared__ float sm[4][NW];
    __shared__ float s_lse[4];

    const int tid  = threadIdx.x;
    const int lane = tid & 31;
    const int warp = tid >> 5;

    int   segs[4];
    int   st[4], en[4];
    bool  go[4];
    #pragma unroll
    for (int k = 0; k < 4; k++) {
        segs[k] = blockIdx.x + k * gridDim.x;
        bool has = (segs[k] < nseg);
        st[k] = has ? ((segs[k] == 0) ? 0 : __ldg(&prefix_sum[segs[k] - 1])) : 0;
        en[k] = has ? __ldg(&prefix_sum[segs[k]]) : 0;
        go[k] = has && (st[k] < en[k]);
    }

    // ---- pass 1 x4: one long load burst ----
    float s[4];
    #pragma unroll
    for (int k = 0; k < 4; k++)
        s[k] = go[k] ? sum_exp_range(logits, st[k], en[k], tid) : 0.0f;

    // ---- joint block reduce: 4 interleaved shuffle chains, one bar round ----
    #pragma unroll
    for (int o = 16; o > 0; o >>= 1) {
        #pragma unroll
        for (int k = 0; k < 4; k++)
            s[k] += __shfl_xor_sync(0xFFFFFFFFu, s[k], o);
    }
    if (lane == 0) {
        #pragma unroll
        for (int k = 0; k < 4; k++) sm[k][warp] = s[k];
    }
    __syncthreads();
    // warp w finishes segment w's reduction (NW == 4)
    {
        float v = (lane < NW) ? sm[warp][lane] : 0.0f;
        #pragma unroll
        for (int o = NW / 2; o > 0; o >>= 1)
            v += __shfl_xor_sync(0xFFFFFFFFu, v, o);
        if (lane == 0) s_lse[warp] = __logf(v);
    }
    __syncthreads();

    // ---- pass 2 x4 ----
    #pragma unroll
    for (int k = 0; k < 4; k++)
        if (go[k]) write_range(logits, out, st[k], en[k], tid, s_lse[k]);
}

extern "C" void kernel_launch(void* const* d_in, const int* in_sizes, int n_in,
                              void* d_out, int out_size) {
    const float* logits     = (const float*)d_in[0];
    const int*   prefix_sum = (const int*)d_in[1];
    float*       out        = (float*)d_out;

    const int num_segs = in_sizes[1];
    const int grid     = (num_segs + 3) / 4;
    jagged_log_softmax_kernel<<<grid, T>>>(logits, prefix_sum, out, num_segs);
}